// round 16
// baseline (speedup 1.0000x reference)
#include <cuda_runtime.h>
#include <cuda_fp16.h>

#define N_NODES 50000
#define N_EDGES 1600000
#define IN_DIM 128
#define OUT_DIM 32
#define HEADS 4
#define HD 128           // HEADS * OUT_DIM
#define EDGE_DIM 16

// ---------------- device scratch (static: no allocation allowed) ----------------
// g_cnt invariant: all-zero at kernel_launch entry. First call: .bss zero-init.
// Every call: k_edge re-zeroes it (after the scan consumed it, before next call's k_hist).
__device__ __half g_hh[N_NODES * HD];         // 12.8 MB  h (fp16)
__device__ unsigned g_Wfrag[8 * 16 * 32 * 2]; // 16 KB: B fragments [kstep][ntile][lane][2]
__device__ float g_asrc[N_NODES * HEADS];
__device__ float g_adst[N_NODES * HEADS];
__device__ int   g_cnt[N_NODES];
__device__ int   g_off[N_NODES + 1];
__device__ int   g_rank[N_EDGES];             // rank of edge within its dst segment
__device__ uint4 g_csr[N_EDGES];              // 25.6 MB: {src, exp01(h2), exp23(h2), pad}

// ---------------- hist: 8 edges/thread + fused W-fragment pack (blocks 0..15) ----------
__global__ void k_hist(const int* __restrict__ ei, const float* __restrict__ W) {
    int i = blockIdx.x * blockDim.x + threadIdx.x;

    if (i < 4096) {   // blocks 0..15: pack W fragments for mma.m16n8k16.row.col B operand
        int l = i & 31;
        int tt = (i >> 5) & 15;
        int s = i >> 9;
        int q = l & 3, g = l >> 2;
        int j = tt * 8 + g;
        int k0 = s * 16 + 2 * q;
        float w00 = W[j * IN_DIM + k0];
        float w01 = W[j * IN_DIM + k0 + 1];
        float w10 = W[j * IN_DIM + k0 + 8];
        float w11 = W[j * IN_DIM + k0 + 9];
        __half2 b0 = __floats2half2_rn(w00, w01);
        __half2 b1 = __floats2half2_rn(w10, w11);
        uint2 o;
        o.x = *(unsigned*)&b0;
        o.y = *(unsigned*)&b1;
        ((uint2*)g_Wfrag)[i] = o;
    }

    if (i < N_EDGES / 8) {
        const int4* dp = (const int4*)(ei + N_EDGES);
        int4 d0 = dp[2 * i];
        int4 d1 = dp[2 * i + 1];
        int4 r0, r1;
        r0.x = atomicAdd(&g_cnt[d0.x], 1);
        r0.y = atomicAdd(&g_cnt[d0.y], 1);
        r0.z = atomicAdd(&g_cnt[d0.z], 1);
        r0.w = atomicAdd(&g_cnt[d0.w], 1);
        r1.x = atomicAdd(&g_cnt[d1.x], 1);
        r1.y = atomicAdd(&g_cnt[d1.y], 1);
        r1.z = atomicAdd(&g_cnt[d1.z], 1);
        r1.w = atomicAdd(&g_cnt[d1.w], 1);
        ((int4*)g_rank)[2 * i]     = r0;
        ((int4*)g_rank)[2 * i + 1] = r1;
    }
}

// ---------------- fused scan (blocks 0..97) + GEMM (blocks 98..488) ----------------
__global__ __launch_bounds__(256) void k_sgemm(const float* __restrict__ x,
                                               const float* __restrict__ att_src,
                                               const float* __restrict__ att_dst) {
    __shared__ __align__(16) __half sh[128 * 136];   // gemm: x tile, later h staging
    __shared__ int shi[256];                          // scan workspace

    int tid = threadIdx.x;
    int b = blockIdx.x;

    if (b < 98) {
        // ---------------- scan block ----------------
        int base = b * 512;
        int s = 0;
        for (int i = tid; i < base; i += 256) s += g_cnt[i];
        shi[tid] = s;
        __syncthreads();
        for (int off = 128; off > 0; off >>= 1) {
            if (tid < off) shi[tid] += shi[tid + off];
            __syncthreads();
        }
        int pre = shi[0];
        __syncthreads();

        int i0 = base + 2 * tid, i1 = i0 + 1;
        int c0 = (i0 < N_NODES) ? g_cnt[i0] : 0;
        int c1 = (i1 < N_NODES) ? g_cnt[i1] : 0;
        int mys = c0 + c1;
        shi[tid] = mys;
        __syncthreads();
        for (int off = 1; off < 256; off <<= 1) {
            int u = (tid >= off) ? shi[tid - off] : 0;
            __syncthreads();
            shi[tid] += u;
            __syncthreads();
        }
        int excl = shi[tid] - mys + pre;
        if (i0 < N_NODES) g_off[i0] = excl;
        if (i1 < N_NODES) g_off[i1] = excl + c0;
        if (b == 0 && tid == 0) g_off[N_NODES] = N_EDGES;
        return;
    }

    // ---------------- gemm block ----------------
    int n0 = (b - 98) * 128;
    int warp = tid >> 5, lane = tid & 31;
    int wm = warp & 3;
    int wn = warp >> 2;
    int q = lane & 3, g = lane >> 2;

    // load + convert x tile: 128 rows x 32 float4s = 4096
#pragma unroll
    for (int r = 0; r < 16; r++) {
        int uidx = r * 256 + tid;
        int row = uidx >> 5, c4 = uidx & 31;
        int gn = n0 + row;
        float4 v = {0.f, 0.f, 0.f, 0.f};
        if (gn < N_NODES) v = *(const float4*)&x[gn * IN_DIM + c4 * 4];
        __half2 p0 = __floats2half2_rn(v.x, v.y);
        __half2 p1 = __floats2half2_rn(v.z, v.w);
        uint2 pk;
        pk.x = *(unsigned*)&p0;
        pk.y = *(unsigned*)&p1;
        *(uint2*)&sh[row * 136 + c4 * 4] = pk;
    }
    __syncthreads();

    float acc[2][8][4];
#pragma unroll
    for (int m = 0; m < 2; m++)
#pragma unroll
        for (int nt = 0; nt < 8; nt++)
#pragma unroll
            for (int c = 0; c < 4; c++) acc[m][nt][c] = 0.f;

    const uint2* wf = (const uint2*)g_Wfrag;
    for (int s = 0; s < 8; s++) {
        unsigned a[2][4];
#pragma unroll
        for (int m = 0; m < 2; m++) {
            int r0 = wm * 32 + m * 16 + g;
            int c0 = s * 16 + 2 * q;
            a[m][0] = *(const unsigned*)&sh[r0 * 136 + c0];
            a[m][1] = *(const unsigned*)&sh[(r0 + 8) * 136 + c0];
            a[m][2] = *(const unsigned*)&sh[r0 * 136 + c0 + 8];
            a[m][3] = *(const unsigned*)&sh[(r0 + 8) * 136 + c0 + 8];
        }
#pragma unroll
        for (int nt = 0; nt < 8; nt++) {
            uint2 bb = wf[(s * 16 + wn * 8 + nt) * 32 + lane];
#pragma unroll
            for (int m = 0; m < 2; m++) {
                asm volatile(
                    "mma.sync.aligned.m16n8k16.row.col.f32.f16.f16.f32 "
                    "{%0,%1,%2,%3}, {%4,%5,%6,%7}, {%8,%9}, {%0,%1,%2,%3};"
                    : "+f"(acc[m][nt][0]), "+f"(acc[m][nt][1]),
                      "+f"(acc[m][nt][2]), "+f"(acc[m][nt][3])
                    : "r"(a[m][0]), "r"(a[m][1]), "r"(a[m][2]), "r"(a[m][3]),
                      "r"(bb.x), "r"(bb.y));
            }
        }
    }

    // fused a_src/a_dst from fp32 fragments
    float2 as2[8], ad2[8];
#pragma unroll
    for (int nt = 0; nt < 8; nt++) {
        int j = wn * 64 + nt * 8 + 2 * q;
        as2[nt] = *(const float2*)&att_src[j];
        ad2[nt] = *(const float2*)&att_dst[j];
    }
#pragma unroll
    for (int m = 0; m < 2; m++) {
        float v[8] = {0.f, 0.f, 0.f, 0.f, 0.f, 0.f, 0.f, 0.f};
#pragma unroll
        for (int nt = 0; nt < 8; nt++) {
            int hsel = (nt >> 2);
            float ax0 = acc[m][nt][0], ax1 = acc[m][nt][1];
            float ay0 = acc[m][nt][2], ay1 = acc[m][nt][3];
            v[0 + hsel] += ax0 * as2[nt].x + ax1 * as2[nt].y;
            v[2 + hsel] += ax0 * ad2[nt].x + ax1 * ad2[nt].y;
            v[4 + hsel] += ay0 * as2[nt].x + ay1 * as2[nt].y;
            v[6 + hsel] += ay0 * ad2[nt].x + ay1 * ad2[nt].y;
        }
#pragma unroll
        for (int k = 0; k < 8; k++) {
            v[k] += __shfl_xor_sync(0xffffffffu, v[k], 1);
            v[k] += __shfl_xor_sync(0xffffffffu, v[k], 2);
        }
        if (q == 0) {
            int node0 = n0 + wm * 32 + m * 16 + g;
            int node1 = node0 + 8;
            if (node0 < N_NODES) {
                g_asrc[node0 * 4 + wn * 2 + 0] = v[0];
                g_asrc[node0 * 4 + wn * 2 + 1] = v[1];
                g_adst[node0 * 4 + wn * 2 + 0] = v[2];
                g_adst[node0 * 4 + wn * 2 + 1] = v[3];
            }
            if (node1 < N_NODES) {
                g_asrc[node1 * 4 + wn * 2 + 0] = v[4];
                g_asrc[node1 * 4 + wn * 2 + 1] = v[5];
                g_adst[node1 * 4 + wn * 2 + 0] = v[6];
                g_adst[node1 * 4 + wn * 2 + 1] = v[7];
            }
        }
    }

    // stage h (fp16) into smem, then coalesced global write
    __syncthreads();
#pragma unroll
    for (int m = 0; m < 2; m++) {
        int r0 = wm * 32 + m * 16 + g;
#pragma unroll
        for (int nt = 0; nt < 8; nt++) {
            int col = wn * 64 + nt * 8 + 2 * q;
            __half2 h0 = __floats2half2_rn(acc[m][nt][0], acc[m][nt][1]);
            __half2 h1 = __floats2half2_rn(acc[m][nt][2], acc[m][nt][3]);
            *(unsigned*)&sh[r0 * 136 + col] = *(unsigned*)&h0;
            *(unsigned*)&sh[(r0 + 8) * 136 + col] = *(unsigned*)&h1;
        }
    }
    __syncthreads();
#pragma unroll
    for (int r = 0; r < 8; r++) {
        int uidx = r * 256 + tid;
        int row = uidx >> 4, c16 = uidx & 15;
        int gn = n0 + row;
        if (gn < N_NODES) {
            uint4 vv = *(const uint4*)&sh[row * 136 + c16 * 8];
            *(uint4*)&g_hh[gn * HD + c16 * 8] = vv;
        }
    }
}

// ---------------- edge pass: 2 edges/thread, phase-separated loads ----------------
// 1600000 = 3125 blocks * 512 edges exactly.
__global__ __launch_bounds__(256) void k_edge(const int* __restrict__ ei,
                                              const float* __restrict__ ea,
                                              const float* __restrict__ Wedge) {
    __shared__ float we[HEADS * EDGE_DIM];
    if (threadIdx.x < HEADS * EDGE_DIM) we[threadIdx.x] = Wedge[threadIdx.x];
    __syncthreads();

    int gidx = blockIdx.x * blockDim.x + threadIdx.x;
    // reset g_cnt for the NEXT launch (scan already consumed it this launch)
    if (gidx < N_NODES) g_cnt[gidx] = 0;

    int eA = blockIdx.x * 512 + threadIdx.x;
    int eB = eA + 256;

    // ---- load phase ----
    int srcA = ei[eA];
    int srcB = ei[eB];
    int dstA = ei[N_EDGES + eA];
    int dstB = ei[N_EDGES + eB];

    const float4* epA = (const float4*)&ea[eA * EDGE_DIM];
    const float4* epB = (const float4*)&ea[eB * EDGE_DIM];
    float4 qa0 = epA[0], qa1 = epA[1], qa2 = epA[2], qa3 = epA[3];
    float4 qb0 = epB[0], qb1 = epB[1], qb2 = epB[2], qb3 = epB[3];

    float4 aA = *(const float4*)&g_asrc[srcA * 4];
    float4 aB = *(const float4*)&g_asrc[srcB * 4];
    float4 bA = *(const float4*)&g_adst[dstA * 4];
    float4 bB = *(const float4*)&g_adst[dstB * 4];
    int rkA = g_rank[eA];
    int rkB = g_rank[eB];
    int ofA = g_off[dstA];
    int ofB = g_off[dstB];

    // ---- compute phase ----
    float evA[16] = {qa0.x, qa0.y, qa0.z, qa0.w, qa1.x, qa1.y, qa1.z, qa1.w,
                     qa2.x, qa2.y, qa2.z, qa2.w, qa3.x, qa3.y, qa3.z, qa3.w};
    float evB[16] = {qb0.x, qb0.y, qb0.z, qb0.w, qb1.x, qb1.y, qb1.z, qb1.w,
                     qb2.x, qb2.y, qb2.z, qb2.w, qb3.x, qb3.y, qb3.z, qb3.w};

    float lgA[4], lgB[4];
#pragma unroll
    for (int h = 0; h < 4; h++) {
        float sA = 0.f, sB = 0.f;
#pragma unroll
        for (int k = 0; k < 16; k++) {
            float w = we[h * 16 + k];
            sA = fmaf(evA[k], w, sA);
            sB = fmaf(evB[k], w, sB);
        }
        lgA[h] = sA;
        lgB[h] = sB;
    }
    lgA[0] += aA.x + bA.x;  lgA[1] += aA.y + bA.y;
    lgA[2] += aA.z + bA.z;  lgA[3] += aA.w + bA.w;
    lgB[0] += aB.x + bB.x;  lgB[1] += aB.y + bB.y;
    lgB[2] += aB.z + bB.z;  lgB[3] += aB.w + bB.w;
#pragma unroll
    for (int h = 0; h < 4; h++) {
        float vA = (lgA[h] > 0.f) ? lgA[h] : 0.2f * lgA[h];
        float vB = (lgB[h] > 0.f) ? lgB[h] : 0.2f * lgB[h];
        lgA[h] = __expf(vA);
        lgB[h] = __expf(vB);
    }

    // ---- store phase ----
    {
        __half2 x01 = __floats2half2_rn(lgA[0], lgA[1]);
        __half2 x23 = __floats2half2_rn(lgA[2], lgA[3]);
        uint4 rec;
        rec.x = (unsigned)srcA;
        rec.y = *(const unsigned*)&x01;
        rec.z = *(const unsigned*)&x23;
        rec.w = 0u;
        g_csr[ofA + rkA] = rec;
    }
    {
        __half2 x01 = __floats2half2_rn(lgB[0], lgB[1]);
        __half2 x23 = __floats2half2_rn(lgB[2], lgB[3]);
        uint4 rec;
        rec.x = (unsigned)srcB;
        rec.y = *(const unsigned*)&x01;
        rec.z = *(const unsigned*)&x23;
        rec.w = 0u;
        g_csr[ofB + rkB] = rec;
    }
}

// ---------------- aggregation: single-pass softmax, NO smem staging ----------------
// All 32 lanes read the SAME CSR record via uniform LDG (L1 broadcast); each lane
// extracts its head's alpha with one PRMT (runtime selector) + one F2F.
__global__ __launch_bounds__(256) void k_agg(const float* __restrict__ bias,
                                             float* __restrict__ out) {
    int warp = threadIdx.x >> 5;
    int lane = threadIdx.x & 31;
    int n = blockIdx.x * 8 + warp;
    if (n >= N_NODES) return;

    int beg = g_off[n];
    int end = g_off[n + 1];
    int myh = lane >> 3;

    // PRMT selector: pick bytes {2*myh, 2*myh+1} from (rec.y, rec.z) into low half
    unsigned psel = (unsigned)(2 * myh) | ((unsigned)(2 * myh + 1) << 4);

    const __half* hh = g_hh + lane * 4;   // this lane's 4 dims
    const uint4* csr = g_csr;

    float4 acc = {0.f, 0.f, 0.f, 0.f};
    float den = 0.f;

    int i = beg;
    for (; i + 8 <= end; i += 8) {
        uint4 r[8];
#pragma unroll
        for (int u = 0; u < 8; u++) r[u] = csr[i + u];   // uniform loads, L1 broadcast
        float av[8];
        uint2 hv[8];
#pragma unroll
        for (int u = 0; u < 8; u++) {
            unsigned pk;
            asm("prmt.b32 %0, %1, %2, %3;" : "=r"(pk) : "r"(r[u].y), "r"(r[u].z), "r"(psel));
            av[u] = __half2float(__ushort_as_half((unsigned short)pk));
            hv[u] = *(const uint2*)&hh[(int)r[u].x * HD];
        }
#pragma unroll
        for (int u = 0; u < 8; u++) {
            float2 f01 = __half22float2(*(const __half2*)&hv[u].x);
            float2 f23 = __half22float2(*(const __half2*)&hv[u].y);
            acc.x = fmaf(av[u], f01.x, acc.x);
            acc.y = fmaf(av[u], f01.y, acc.y);
            acc.z = fmaf(av[u], f23.x, acc.z);
            acc.w = fmaf(av[u], f23.y, acc.w);
            den += av[u];
        }
    }
    for (; i < end; i++) {
        uint4 r = csr[i];
        unsigned pk;
        asm("prmt.b32 %0, %1, %2, %3;" : "=r"(pk) : "r"(r.y), "r"(r.z), "r"(psel));
        float a = __half2float(__ushort_as_half((unsigned short)pk));
        uint2 hv = *(const uint2*)&hh[(int)r.x * HD];
        float2 f01 = __half22float2(*(const __half2*)&hv.x);
        float2 f23 = __half22float2(*(const __half2*)&hv.y);
        acc.x = fmaf(a, f01.x, acc.x);
        acc.y = fmaf(a, f01.y, acc.y);
        acc.z = fmaf(a, f23.x, acc.z);
        acc.w = fmaf(a, f23.y, acc.w);
        den += a;
    }

    // normalize by this head's denominator
    float inv = 1.f / (den + 1e-16f);
    acc.x *= inv;
    acc.y *= inv;
    acc.z *= inv;
    acc.w *= inv;

    // reduce over heads (lanes l, l^8, l^16, l^24 hold heads 0..3, same dims)
    acc.x += __shfl_xor_sync(0xffffffffu, acc.x, 8);
    acc.y += __shfl_xor_sync(0xffffffffu, acc.y, 8);
    acc.z += __shfl_xor_sync(0xffffffffu, acc.z, 8);
    acc.w += __shfl_xor_sync(0xffffffffu, acc.w, 8);
    acc.x += __shfl_xor_sync(0xffffffffu, acc.x, 16);
    acc.y += __shfl_xor_sync(0xffffffffu, acc.y, 16);
    acc.z += __shfl_xor_sync(0xffffffffu, acc.z, 16);
    acc.w += __shfl_xor_sync(0xffffffffu, acc.w, 16);

    if (lane < 8) {
        float4 b4 = *(const float4*)&bias[lane * 4];
        float4 o;
        o.x = acc.x * 0.25f + b4.x;
        o.y = acc.y * 0.25f + b4.y;
        o.z = acc.z * 0.25f + b4.z;
        o.w = acc.w * 0.25f + b4.w;
        *(float4*)&out[n * OUT_DIM + lane * 4] = o;
    }
}

// ---------------- launch: 4 kernels; index 3 (k_agg) is the profiled one ----------------
extern "C" void kernel_launch(void* const* d_in, const int* in_sizes, int n_in,
                              void* d_out, int out_size) {
    const float* x    = (const float*)d_in[0];
    const int*   ei   = (const int*)  d_in[1];
    const float* ea   = (const float*)d_in[2];
    const float* Wl   = (const float*)d_in[3];
    const float* as   = (const float*)d_in[4];
    const float* ad   = (const float*)d_in[5];
    const float* bias = (const float*)d_in[6];
    const float* We   = (const float*)d_in[7];
    float* out = (float*)d_out;

    k_hist  <<<(N_EDGES / 8 + 255) / 256, 256>>>(ei, Wl);
    k_sgemm <<<98 + (N_NODES + 127) / 128, 256>>>(x, as, ad);
    k_edge  <<<3125, 256>>>(ei, ea, We);
    k_agg   <<<(N_NODES + 7) / 8, 256>>>(bias, out);
}